// round 15
// baseline (speedup 1.0000x reference)
#include <cuda_runtime.h>
#include <math.h>
#include <stdint.h>

#define B_    64
#define T_    1000
#define D_    512
#define V_    29
#define L_    200
#define CBLANK 28
#define LOG2E 1.44269504088896340736f
#define LN2   0.69314718055994530942f
#define ESENT (-(1 << 29))

#define CHUNK  125
#define NCHUNK 8
#define NGEMM  (NCHUNK * B_)     // 512 producer blocks
#define GRID_F (B_ + NGEMM)      // 576 blocks
#define NTHR   256

typedef unsigned long long u64;

// ---------------- device scratch (no allocations allowed) ----------------
__device__ float d_lp[(long)B_ * T_ * V_];   // LINEAR probs p[b][t][v]
__device__ float d_loss[B_];
__device__ float d_wT[32 * 512];             // transposed W (built by CTC blocks)
__device__ int   d_flag[NCHUNK * B_];        // [chunk][sample] ready flags
__device__ int   d_wcnt;                     // W-transpose completion count
__device__ int   d_pdone;                    // producer completion count
__device__ int   d_done;                     // CTC completion count

__device__ __forceinline__ float ex2f(float x){ float r; asm("ex2.approx.f32 %0, %1;" : "=f"(r) : "f"(x)); return r; }
__device__ __forceinline__ float lg2f(float x){ float r; asm("lg2.approx.f32 %0, %1;" : "=f"(r) : "f"(x)); return r; }

#define FMA2(d, a, b) asm("fma.rn.f32x2 %0, %1, %2, %0;" : "+l"(d) : "l"(a), "l"(b))

// ---- linear (mantissa, int-exponent) arithmetic (proven R11/R13/R14) ----
struct ME { float m; int E; };

__device__ __forceinline__ float mkscale(int d) {
    return __uint_as_float((unsigned)max(d + 127, 0) << 23);
}
__device__ __forceinline__ ME me_renorm(float v, int Em) {
    const unsigned bits = __float_as_uint(v);
    ME r;
    r.E = Em + (int)(bits >> 23) - 127;
    r.m = __uint_as_float((bits & 0x007fffffu) | 0x3f800000u);
    return r;
}
__device__ __forceinline__ ME me_split(float v) { return me_renorm(v, 0); }
__device__ __forceinline__ ME upd2(ME a, ME b, float p) {
    const int Em = max(a.E, b.E);
    const float sum = fmaf(a.m, mkscale(a.E - Em), b.m * mkscale(b.E - Em));
    return me_renorm(p * sum, Em);
}
__device__ __forceinline__ ME upd3(ME a, ME b, ME c, bool sk, float p) {
    const int Ec = sk ? c.E : ESENT;
    const int Em = max(a.E, max(b.E, Ec));
    const float sum = fmaf(a.m, mkscale(a.E - Em),
                      fmaf(b.m, mkscale(b.E - Em), c.m * mkscale(Ec - Em)));
    return me_renorm(p * sum, Em);
}

// ---- sync helpers ----
__device__ __forceinline__ int ld_acq(const int* p) {
    int v;
    asm volatile("ld.acquire.gpu.global.b32 %0, [%1];" : "=r"(v) : "l"(p) : "memory");
    return v;
}
__device__ __forceinline__ void st_rel(int* p, int v) {
    asm volatile("st.release.gpu.global.b32 [%0], %1;" :: "l"(p), "r"(v) : "memory");
}

// =====================================================================
// Fused single kernel: blocks [0,64) CTC consumers (+W transpose +final
// reduce), [64,576) GEMM producers. 256 threads/block, smem 42496B.
// =====================================================================
#define SMEM_FUSED 42496
extern __shared__ char smem_dyn[];

__device__ void gemm_path(const float* __restrict__ F,
                          const float* __restrict__ bias)
{
    float* fbuf = (float*)smem_dyn;                  // 2 x 128x32 f (32768B)
    float* wt   = (float*)(smem_dyn + 32768);        // 2 x 32x36 f  (9216B)
    float* csh  = (float*)(smem_dyn + 41984);        // 128 f
    float* lbuf = fbuf;                              // epilogue reuse

    const int tid = threadIdx.x;
    const int gb  = blockIdx.x - B_;
    const int c   = gb >> 6;          // chunk 0..7
    const int b   = gb & 63;          // sample
    const long rowBase = (long)b * T_ + c * CHUNK;
    const uint32_t fsh  = (uint32_t)__cvta_generic_to_shared(fbuf);
    const uint32_t wtsh = (uint32_t)__cvta_generic_to_shared(wt);

    // wait for W transpose (done by CTC blocks)
    if (tid == 0) { while (ld_acq(&d_wcnt) < B_) __nanosleep(64); }
    __syncthreads();

    auto prefetch = [&](int kci, int st) {
        const uint32_t sbase = fsh + (uint32_t)st * 16384u;
#pragma unroll
        for (int m = 0; m < 4; m++) {
            const int q  = tid + NTHR * m;           // 0..1023
            const int r  = q >> 3;
            const int kq = q & 7;
            long row = rowBase + r;
            if (row > (long)B_ * T_ - 1) row = (long)B_ * T_ - 1;
            const float* src = F + row * D_ + kci * 32 + kq * 4;
            const uint32_t dst = sbase +
                (uint32_t)((r * 32 + ((kq ^ ((r >> 2) & 7)) << 2)) * 4);
            asm volatile("cp.async.ca.shared.global [%0], [%1], 16;" :: "r"(dst), "l"(src));
        }
        const uint32_t wbase = wtsh + (uint32_t)st * 4608u;
        {
            const int col = tid >> 3;                // 0..31
            const int kq  = tid & 7;
            const float* src = d_wT + col * 512 + kci * 32 + kq * 4;
            const uint32_t dst = wbase + (uint32_t)((col * 36 + kq * 4) * 4);
            asm volatile("cp.async.ca.shared.global [%0], [%1], 16;" :: "r"(dst), "l"(src));
        }
    };

    prefetch(0, 0);
    asm volatile("cp.async.commit_group;");

    const int rg = tid >> 3;          // 0..31 : rows rg*4 + i
    const int cg = tid & 7;           // 0..7  : cols cg + 8*j
    const int fkey = (rg & 7) << 2;   // = ((row>>2)&7)<<2, row = rg*4+i

    float bv[4];
#pragma unroll
    for (int j = 0; j < 4; j++) { int cc = cg + 8 * j; bv[j] = (cc < V_) ? bias[cc] : 0.f; }

    u64 acc[4][4];
#pragma unroll
    for (int i = 0; i < 4; i++)
#pragma unroll
        for (int j = 0; j < 4; j++) acc[i][j] = 0ull;

    for (int kci = 0; kci < 16; kci++) {
        if (kci < 15) prefetch(kci + 1, (kci + 1) & 1);
        asm volatile("cp.async.commit_group;");
        asm volatile("cp.async.wait_group 1;");
        __syncthreads();

        const float* fstage = fbuf + (kci & 1) * 4096;
        const float* wstage = wt   + (kci & 1) * 1152;
#pragma unroll
        for (int kq = 0; kq < 8; kq++) {
            ulonglong2 f[4], w4[4];
#pragma unroll
            for (int i = 0; i < 4; i++)
                f[i] = *reinterpret_cast<const ulonglong2*>(
                    fstage + (rg * 4 + i) * 32 + ((kq << 2) ^ fkey));
#pragma unroll
            for (int j = 0; j < 4; j++)
                w4[j] = *reinterpret_cast<const ulonglong2*>(
                    wstage + (cg + 8 * j) * 36 + kq * 4);
#pragma unroll
            for (int i = 0; i < 4; i++)
#pragma unroll
                for (int j = 0; j < 4; j++) FMA2(acc[i][j], f[i].x, w4[j].x);
#pragma unroll
            for (int i = 0; i < 4; i++)
#pragma unroll
                for (int j = 0; j < 4; j++) FMA2(acc[i][j], f[i].y, w4[j].y);
        }
        __syncthreads();
    }

    // epilogue: combine k-pairs, bias, logits to smem [128][33]
#pragma unroll
    for (int i = 0; i < 4; i++)
#pragma unroll
        for (int j = 0; j < 4; j++) {
            const float lo = __uint_as_float((unsigned)(acc[i][j] & 0xffffffffull));
            const float hi = __uint_as_float((unsigned)(acc[i][j] >> 32));
            lbuf[(rg * 4 + i) * 33 + (cg + 8 * j)] = lo + hi + bv[j];
        }
    __syncthreads();

    if (tid < CHUNK) {
        const float* r = &lbuf[tid * 33];
        float m = r[0];
#pragma unroll
        for (int v = 1; v < V_; v++) m = fmaxf(m, r[v]);
        float sum = 0.f;
#pragma unroll
        for (int v = 0; v < V_; v++) sum += ex2f((r[v] - m) * LOG2E);
        csh[tid] = m * LOG2E + lg2f(sum);
    }
    __syncthreads();

    float* outp = d_lp + rowBase * V_;
    for (int i = tid; i < CHUNK * V_; i += NTHR) {
        const int row = i / V_;
        const int v   = i - row * V_;
        outp[i] = ex2f(lbuf[row * 33 + v] * LOG2E - csh[row]);
    }

    __threadfence();
    __syncthreads();
    if (tid == 0) {
        st_rel(&d_flag[c * B_ + b], 1);
        __threadfence();
        atomicAdd(&d_pdone, 1);
    }
}

struct PFv { float B0, B1, p10, p11, p30, p31, V0; };

__device__ void ctc_path(const float* __restrict__ W,
                         const int* __restrict__ labels,
                         const int* __restrict__ flens,
                         const int* __restrict__ llens,
                         float* __restrict__ out)
{
    float4* pm     = (float4*)smem_dyn;              // [2][264]
    float4* pe     = pm + 2 * 264;                   // [2][264]
    int*    lab_sh = (int*)(pe + 2 * 264);           // [200]
    float*  afin   = (float*)(lab_sh + L_);          // [416]
    int*    fin    = (int*)(afin + 416);

    const int b    = blockIdx.x;
    const int tid  = threadIdx.x;
    const int flen = flens[b];
    const int llen = llens[b];

    // ---- W transpose slice: 64 blocks x 256 thr = 16384 = 32x512 ----
    {
        const int idx = b * NTHR + tid;
        const int c = idx & 31, k = idx >> 5;
        d_wT[c * 512 + k] = (c < V_) ? W[k * V_ + c] : 0.f;
        __threadfence();
        __syncthreads();
        if (tid == 0) atomicAdd(&d_wcnt, 1);
    }

    if (tid < L_) lab_sh[tid] = labels[b * L_ + tid];
    if (tid == 0) {
        const float4 mpad = make_float4(1.f, 1.f, 1.f, 1.f);
        const float  es   = __int_as_float(ESENT);
        const float4 epad = make_float4(es, es, es, es);
        pm[0] = mpad; pm[264] = mpad;
        pe[0] = epad; pe[264] = epad;
    }
    __syncthreads();

    const int i  = tid;                              // >101 = dummy lanes
    const int j1 = min(2 * i,     L_ - 1);
    const int j3 = min(2 * i + 1, L_ - 1);
    const int jv = min(max(2 * i - 1, 0), L_ - 1);
    const int e1 = lab_sh[j1];
    const int e3 = lab_sh[j3];
    const int eV = lab_sh[jv];
    const bool skip1 = (i >= 1) && (e1 != lab_sh[j1 - 1]);
    const bool skip3 = (e3 != lab_sh[j3 - 1]);
    const bool skipv = (i >= 1) && (eV != lab_sh[jv - 1]);

    const float* lpb = d_lp + (long)b * T_ * V_;
    int ready = 0;

    auto wait_rows = [&](int row) {
        const int need = row / CHUNK;
        while (ready <= need) {
            if (ld_acq(&d_flag[ready * B_ + b])) ready++;
            else __nanosleep(128);
        }
    };
    auto loadPF = [&](int tt) {
        PFv f;
        const int r0c = min(tt,     T_ - 1);
        const int r1c = min(tt + 1, T_ - 1);
        wait_rows(r1c);
        const int r0 = r0c * V_, r1 = r1c * V_;
        f.B0 = lpb[r0 + CBLANK]; f.p10 = lpb[r0 + e1];
        f.p30 = lpb[r0 + e3];    f.V0  = lpb[r0 + eV];
        f.B1 = lpb[r1 + CBLANK]; f.p11 = lpb[r1 + e1]; f.p31 = lpb[r1 + e3];
        return f;
    };

    wait_rows(0);
    ME a0 = {1.f, ESENT}, a1 = {1.f, ESENT}, a2 = {1.f, ESENT}, a3 = {1.f, ESENT};
    if (i == 0) { a0 = me_split(lpb[CBLANK]); a1 = me_split(lpb[e1]); }
    pm[i + 1] = make_float4(a0.m, a1.m, a2.m, a3.m);
    pe[i + 1] = make_float4(__int_as_float(a0.E), __int_as_float(a1.E),
                            __int_as_float(a2.E), __int_as_float(a3.E));

    PFv f0 = loadPF(1);
    PFv f1 = loadPF(3);
    __syncthreads();

    int cur = 0;
    int t = 1;

#define CTC_ITER(F) do {                                                         \
    const float4 nm  = pm[cur * 264 + i];                                        \
    const float4 neb = pe[cur * 264 + i];                                        \
    const ME n1 = {nm.y, __float_as_int(neb.y)};                                 \
    const ME n2 = {nm.z, __float_as_int(neb.z)};                                 \
    const ME n3 = {nm.w, __float_as_int(neb.w)};                                 \
    const ME b0 = upd2(a0, n3, F.B0);                                            \
    const ME l1 = upd3(a1, a0, n3, skip1, F.p10);                                \
    const ME b2 = upd2(a2, a1, F.B0);                                            \
    const ME l3 = upd3(a3, a2, a1, skip3, F.p30);                                \
    const ME vv = upd3(n3, n2, n1, skipv, F.V0);                                 \
    a0 = upd2(b0, vv, F.B1);                                                     \
    a1 = upd3(l1, b0, vv, skip1, F.p11);                                         \
    a2 = upd2(b2, l1, F.B1);                                                     \
    a3 = upd3(l3, b2, l1, skip3, F.p31);                                         \
    pm[(cur ^ 1) * 264 + i + 1] = make_float4(a0.m, a1.m, a2.m, a3.m);           \
    pe[(cur ^ 1) * 264 + i + 1] = make_float4(                                   \
        __int_as_float(a0.E), __int_as_float(a1.E),                              \
        __int_as_float(a2.E), __int_as_float(a3.E));                             \
    cur ^= 1;                                                                    \
    __syncthreads();                                                             \
    t += 2;                                                                      \
} while (0)

    while (t + 3 < flen) {
        CTC_ITER(f0); f0 = loadPF(t + 2);
        CTC_ITER(f1); f1 = loadPF(t + 2);
    }
    while (t + 1 < flen) {
        CTC_ITER(f0);
        f0 = f1; f1 = loadPF(t + 2);
    }
    if (t < flen) {
        const float4 nm  = pm[cur * 264 + i];
        const float4 neb = pe[cur * 264 + i];
        const ME n3 = {nm.w, __float_as_int(neb.w)};
        const ME b0 = upd2(a0, n3, f0.B0);
        const ME l1 = upd3(a1, a0, n3, skip1, f0.p10);
        const ME b2 = upd2(a2, a1, f0.B0);
        const ME l3 = upd3(a3, a2, a1, skip3, f0.p30);
        a0 = b0; a1 = l1; a2 = b2; a3 = l3;
    }
#undef CTC_ITER

    __syncthreads();
    if (i <= 101) {
        afin[4 * i + 0] = (float)a0.E + lg2f(a0.m);
        afin[4 * i + 1] = (float)a1.E + lg2f(a1.m);
        afin[4 * i + 2] = (float)a2.E + lg2f(a2.m);
        afin[4 * i + 3] = (float)a3.E + lg2f(a3.m);
    }
    __syncthreads();

    if (tid == 0) {
        const float l1 = afin[2 * llen];
        const float l2 = afin[2 * llen - 1];
        const float mx = fmaxf(l1, l2), mn = fminf(l1, l2);
        const float ls = mx + lg2f(1.0f + ex2f(mn - mx));
        const float nll = -ls * LN2;
        d_loss[b] = (nll < 5e8f) ? nll / (float)llen : 0.f;
    }

    // ---- last CTC block: final reduce + state reset for next replay ----
    __threadfence();
    __syncthreads();
    if (tid == 0) *fin = (atomicAdd(&d_done, 1) == B_ - 1) ? 1 : 0;
    __syncthreads();
    if (*fin) {
        if (tid == 0) { while (ld_acq(&d_pdone) < NGEMM) __nanosleep(128); }
        __syncthreads();
        __threadfence();
        for (int k = tid; k < NCHUNK * B_; k += NTHR) d_flag[k] = 0;
        if (tid == 0) {
            d_pdone = 0; d_done = 0; d_wcnt = 0;
            float s = 0.f;
            for (int q = 0; q < B_; q++) s += d_loss[q];
            out[0] = s * (1.f / (float)B_);
        }
    }
}

__global__ __launch_bounds__(NTHR, 2) void fused_kernel(
    const float* __restrict__ F, const float* __restrict__ W,
    const float* __restrict__ bias,
    const int* __restrict__ labels, const int* __restrict__ flens,
    const int* __restrict__ llens, float* __restrict__ out)
{
    if (blockIdx.x < B_) ctc_path(W, labels, flens, llens, out);
    else                 gemm_path(F, bias);
}

// =====================================================================
extern "C" void kernel_launch(void* const* d_in, const int* in_sizes, int n_in,
                              void* d_out, int out_size)
{
    (void)in_sizes; (void)n_in; (void)out_size;
    const float* F      = (const float*)d_in[0];
    const float* W      = (const float*)d_in[1];
    const float* bias   = (const float*)d_in[2];
    const int*   labels = (const int*)d_in[3];
    const int*   flens  = (const int*)d_in[4];
    const int*   llens  = (const int*)d_in[5];
    float* out = (float*)d_out;

    cudaFuncSetAttribute(fused_kernel,
                         cudaFuncAttributeMaxDynamicSharedMemorySize, SMEM_FUSED);

    fused_kernel<<<GRID_F, NTHR, SMEM_FUSED>>>(F, W, bias, labels, flens, llens, out);
}

// round 16
// speedup vs baseline: 1.2250x; 1.2250x over previous
#include <cuda_runtime.h>
#include <math.h>
#include <stdint.h>

#define B_    64
#define T_    1000
#define D_    512
#define V_    29
#define L_    200
#define CBLANK 28
#define LOG2E 1.44269504088896340736f
#define LN2   0.69314718055994530942f
#define ESENT (-(1 << 29))

#define CHUNK  50
#define NCHUNK 20                 // 1000 / 50
#define NGEMM  (NCHUNK * B_)      // 1280 producer blocks
#define GRID_F (B_ + NGEMM)       // 1344 blocks
#define ROWS_T 64                 // producer tile height (>= CHUNK)

typedef unsigned long long u64;

// ---------------- device scratch (no allocations allowed) ----------------
__device__ float d_lp[(long)B_ * T_ * V_];   // LINEAR probs p[b][t][v]
__device__ float d_loss[B_];
__device__ float d_wT[32 * 512];             // transposed W (pre-kernel)
__device__ int   d_flag[NCHUNK * B_];        // [chunk][sample] ready flags
__device__ int   d_done;                     // CTC completion ticket

__device__ __forceinline__ float ex2f(float x){ float r; asm("ex2.approx.f32 %0, %1;" : "=f"(r) : "f"(x)); return r; }
__device__ __forceinline__ float lg2f(float x){ float r; asm("lg2.approx.f32 %0, %1;" : "=f"(r) : "f"(x)); return r; }

#define FMA2(d, a, b) asm("fma.rn.f32x2 %0, %1, %2, %0;" : "+l"(d) : "l"(a), "l"(b))

// ---- linear (mantissa, int-exponent) arithmetic (proven R11/R13/R14) ----
struct ME { float m; int E; };

__device__ __forceinline__ float mkscale(int d) {
    return __uint_as_float((unsigned)max(d + 127, 0) << 23);
}
__device__ __forceinline__ ME me_renorm(float v, int Em) {
    const unsigned bits = __float_as_uint(v);
    ME r;
    r.E = Em + (int)(bits >> 23) - 127;
    r.m = __uint_as_float((bits & 0x007fffffu) | 0x3f800000u);
    return r;
}
__device__ __forceinline__ ME me_split(float v) { return me_renorm(v, 0); }
__device__ __forceinline__ ME upd2(ME a, ME b, float p) {
    const int Em = max(a.E, b.E);
    const float sum = fmaf(a.m, mkscale(a.E - Em), b.m * mkscale(b.E - Em));
    return me_renorm(p * sum, Em);
}
__device__ __forceinline__ ME upd3(ME a, ME b, ME c, bool sk, float p) {
    const int Ec = sk ? c.E : ESENT;
    const int Em = max(a.E, max(b.E, Ec));
    const float sum = fmaf(a.m, mkscale(a.E - Em),
                      fmaf(b.m, mkscale(b.E - Em), c.m * mkscale(Ec - Em)));
    return me_renorm(p * sum, Em);
}

// ---- sync helpers ----
__device__ __forceinline__ int ld_acq(const int* p) {
    int v;
    asm volatile("ld.acquire.gpu.global.b32 %0, [%1];" : "=r"(v) : "l"(p) : "memory");
    return v;
}
__device__ __forceinline__ void st_rel(int* p, int v) {
    asm volatile("st.release.gpu.global.b32 [%0], %1;" :: "l"(p), "r"(v) : "memory");
}

// =====================================================================
// Pre-kernel: zero flags + ticket, transpose W into d_wT[32][512].
// =====================================================================
__global__ __launch_bounds__(128) void pre_kernel(const float* __restrict__ W)
{
    const int bid = blockIdx.x, tid = threadIdx.x;
    if (bid < 32) {
        for (int k = tid; k < 512; k += 128)
            d_wT[bid * 512 + k] = (bid < V_) ? W[k * V_ + bid] : 0.f;
    } else {
        for (int i = tid; i < NCHUNK * B_; i += 128) d_flag[i] = 0;
        if (tid == 0) d_done = 0;
    }
}

// =====================================================================
// Fused kernel: blocks [0,64) = CTC consumers (+final reduce),
// [64,1344) = GEMM producers. 128 threads/block, smem 26112B.
// =====================================================================
#define SMEM_FUSED 26112
extern __shared__ char smem_dyn[];

__device__ void gemm_path(const float* __restrict__ F,
                          const float* __restrict__ bias)
{
    float* fbuf = (float*)smem_dyn;                  // 2 x 64x32 f (16384B)
    float* wt   = (float*)(smem_dyn + 16384);        // 2 x 32x36 f (9216B)
    float* csh  = (float*)(smem_dyn + 25600);        // 64 f
    float* lbuf = fbuf;                              // epilogue reuse

    const int tid = threadIdx.x;
    const int gb  = blockIdx.x - B_;
    const int c   = gb >> 6;          // chunk 0..19
    const int b   = gb & 63;          // sample
    const long rowBase = (long)b * T_ + c * CHUNK;
    const uint32_t fsh  = (uint32_t)__cvta_generic_to_shared(fbuf);
    const uint32_t wtsh = (uint32_t)__cvta_generic_to_shared(wt);

    auto prefetch = [&](int kci, int st) {
        const uint32_t sbase = fsh + (uint32_t)st * 8192u;
#pragma unroll
        for (int m = 0; m < 4; m++) {
            const int q  = tid + 128 * m;            // 0..511
            const int r  = q >> 3;                   // 0..63
            const int kq = q & 7;
            long row = rowBase + r;
            if (row > (long)B_ * T_ - 1) row = (long)B_ * T_ - 1;   // tail clamp
            const float* src = F + row * D_ + kci * 32 + kq * 4;
            const uint32_t dst = sbase +
                (uint32_t)((r * 32 + ((kq ^ ((r >> 2) & 7)) << 2)) * 4);
            asm volatile("cp.async.ca.shared.global [%0], [%1], 16;" :: "r"(dst), "l"(src));
        }
        const uint32_t wbase = wtsh + (uint32_t)st * 4608u;
#pragma unroll
        for (int m = 0; m < 2; m++) {
            const int q   = tid + 128 * m;           // 0..255
            const int col = q >> 3;
            const int kq  = q & 7;
            const float* src = d_wT + col * 512 + kci * 32 + kq * 4;
            const uint32_t dst = wbase + (uint32_t)((col * 36 + kq * 4) * 4);
            asm volatile("cp.async.ca.shared.global [%0], [%1], 16;" :: "r"(dst), "l"(src));
        }
    };

    prefetch(0, 0);
    asm volatile("cp.async.commit_group;");

    const int rg = tid >> 3;          // 0..15 : rows rg*4 + i
    const int cg = tid & 7;           // 0..7  : cols cg + 8*j
    const int fkey = (rg & 7) << 2;   // ((row>>2)&7)<<2 with row = rg*4+i

    float bv[4];
#pragma unroll
    for (int j = 0; j < 4; j++) { int cc = cg + 8 * j; bv[j] = (cc < V_) ? bias[cc] : 0.f; }

    u64 acc[4][4];
#pragma unroll
    for (int i = 0; i < 4; i++)
#pragma unroll
        for (int j = 0; j < 4; j++) acc[i][j] = 0ull;

    for (int kci = 0; kci < 16; kci++) {
        if (kci < 15) prefetch(kci + 1, (kci + 1) & 1);
        asm volatile("cp.async.commit_group;");
        asm volatile("cp.async.wait_group 1;");
        __syncthreads();

        const float* fstage = fbuf + (kci & 1) * 2048;
        const float* wstage = wt   + (kci & 1) * 1152;
#pragma unroll
        for (int kq = 0; kq < 8; kq++) {
            ulonglong2 f[4], w4[4];
#pragma unroll
            for (int i = 0; i < 4; i++)
                f[i] = *reinterpret_cast<const ulonglong2*>(
                    fstage + (rg * 4 + i) * 32 + ((kq << 2) ^ fkey));
#pragma unroll
            for (int j = 0; j < 4; j++)
                w4[j] = *reinterpret_cast<const ulonglong2*>(
                    wstage + (cg + 8 * j) * 36 + kq * 4);
#pragma unroll
            for (int i = 0; i < 4; i++)
#pragma unroll
                for (int j = 0; j < 4; j++) FMA2(acc[i][j], f[i].x, w4[j].x);
#pragma unroll
            for (int i = 0; i < 4; i++)
#pragma unroll
                for (int j = 0; j < 4; j++) FMA2(acc[i][j], f[i].y, w4[j].y);
        }
        __syncthreads();
    }

    // epilogue: combine k-pairs, bias, logits to smem [64][33]
#pragma unroll
    for (int i = 0; i < 4; i++)
#pragma unroll
        for (int j = 0; j < 4; j++) {
            const float lo = __uint_as_float((unsigned)(acc[i][j] & 0xffffffffull));
            const float hi = __uint_as_float((unsigned)(acc[i][j] >> 32));
            lbuf[(rg * 4 + i) * 33 + (cg + 8 * j)] = lo + hi + bv[j];
        }
    __syncthreads();

    if (tid < CHUNK) {
        const float* r = &lbuf[tid * 33];
        float m = r[0];
#pragma unroll
        for (int v = 1; v < V_; v++) m = fmaxf(m, r[v]);
        float sum = 0.f;
#pragma unroll
        for (int v = 0; v < V_; v++) sum += ex2f((r[v] - m) * LOG2E);
        csh[tid] = m * LOG2E + lg2f(sum);
    }
    __syncthreads();

    float* outp = d_lp + rowBase * V_;
    for (int i = tid; i < CHUNK * V_; i += 128) {
        const int row = i / V_;
        const int v   = i - row * V_;
        outp[i] = ex2f(lbuf[row * 33 + v] * LOG2E - csh[row]);
    }

    __threadfence();
    __syncthreads();
    if (tid == 0) st_rel(&d_flag[c * B_ + b], 1);
}

struct PFv { float B0, B1, p10, p11, p30, p31, V0; };

__device__ void ctc_path(const int* __restrict__ labels,
                         const int* __restrict__ flens,
                         const int* __restrict__ llens,
                         float* __restrict__ out)
{
    float4* pm     = (float4*)smem_dyn;              // [2][132]
    float4* pe     = pm + 2 * 132;                   // [2][132]
    int*    lab_sh = (int*)(pe + 2 * 132);           // [200]
    float*  afin   = (float*)(lab_sh + L_);          // [520]
    int*    fin    = (int*)(afin + 520);

    const int b    = blockIdx.x;
    const int tid  = threadIdx.x;
    const int flen = flens[b];
    const int llen = llens[b];

    for (int k = tid; k < L_; k += 128) lab_sh[k] = labels[b * L_ + k];
    if (tid == 0) {
        const float4 mpad = make_float4(1.f, 1.f, 1.f, 1.f);
        const float  es   = __int_as_float(ESENT);
        const float4 epad = make_float4(es, es, es, es);
        pm[0] = mpad; pm[132] = mpad;
        pe[0] = epad; pe[132] = epad;
    }
    __syncthreads();

    const int i  = tid;
    const int j1 = min(2 * i,     L_ - 1);
    const int j3 = min(2 * i + 1, L_ - 1);
    const int jv = min(max(2 * i - 1, 0), L_ - 1);
    const int e1 = lab_sh[j1];
    const int e3 = lab_sh[j3];
    const int eV = lab_sh[jv];
    const bool skip1 = (i >= 1) && (e1 != lab_sh[j1 - 1]);
    const bool skip3 = (e3 != lab_sh[j3 - 1]);
    const bool skipv = (i >= 1) && (eV != lab_sh[jv - 1]);

    const float* lpb = d_lp + (long)b * T_ * V_;
    int ready = 0;

    auto wait_rows = [&](int row) {
        const int need = row / CHUNK;
        while (ready <= need) {
            if (ld_acq(&d_flag[ready * B_ + b])) ready++;
            else __nanosleep(128);
        }
    };
    auto loadPF = [&](int tt) {
        PFv f;
        const int r0c = min(tt,     T_ - 1);
        const int r1c = min(tt + 1, T_ - 1);
        wait_rows(r1c);
        const int r0 = r0c * V_, r1 = r1c * V_;
        f.B0 = lpb[r0 + CBLANK]; f.p10 = lpb[r0 + e1];
        f.p30 = lpb[r0 + e3];    f.V0  = lpb[r0 + eV];
        f.B1 = lpb[r1 + CBLANK]; f.p11 = lpb[r1 + e1]; f.p31 = lpb[r1 + e3];
        return f;
    };

    wait_rows(0);
    ME a0 = {1.f, ESENT}, a1 = {1.f, ESENT}, a2 = {1.f, ESENT}, a3 = {1.f, ESENT};
    if (i == 0) { a0 = me_split(lpb[CBLANK]); a1 = me_split(lpb[e1]); }
    pm[i + 1] = make_float4(a0.m, a1.m, a2.m, a3.m);
    pe[i + 1] = make_float4(__int_as_float(a0.E), __int_as_float(a1.E),
                            __int_as_float(a2.E), __int_as_float(a3.E));

    PFv f0 = loadPF(1);
    PFv f1 = loadPF(3);
    __syncthreads();

    int cur = 0;
    int t = 1;

#define CTC_ITER(F) do {                                                         \
    const float4 nm  = pm[cur * 132 + i];                                        \
    const float4 neb = pe[cur * 132 + i];                                        \
    const ME n1 = {nm.y, __float_as_int(neb.y)};                                 \
    const ME n2 = {nm.z, __float_as_int(neb.z)};                                 \
    const ME n3 = {nm.w, __float_as_int(neb.w)};                                 \
    const ME b0 = upd2(a0, n3, F.B0);                                            \
    const ME l1 = upd3(a1, a0, n3, skip1, F.p10);                                \
    const ME b2 = upd2(a2, a1, F.B0);                                            \
    const ME l3 = upd3(a3, a2, a1, skip3, F.p30);                                \
    const ME vv = upd3(n3, n2, n1, skipv, F.V0);                                 \
    a0 = upd2(b0, vv, F.B1);                                                     \
    a1 = upd3(l1, b0, vv, skip1, F.p11);                                         \
    a2 = upd2(b2, l1, F.B1);                                                     \
    a3 = upd3(l3, b2, l1, skip3, F.p31);                                         \
    pm[(cur ^ 1) * 132 + i + 1] = make_float4(a0.m, a1.m, a2.m, a3.m);           \
    pe[(cur ^ 1) * 132 + i + 1] = make_float4(                                   \
        __int_as_float(a0.E), __int_as_float(a1.E),                              \
        __int_as_float(a2.E), __int_as_float(a3.E));                             \
    cur ^= 1;                                                                    \
    __syncthreads();                                                             \
    t += 2;                                                                      \
} while (0)

    while (t + 3 < flen) {
        CTC_ITER(f0); f0 = loadPF(t + 2);
        CTC_ITER(f1); f1 = loadPF(t + 2);
    }
    while (t + 1 < flen) {
        CTC_ITER(f0);
        f0 = f1; f1 = loadPF(t + 2);
    }
    if (t < flen) {
        const float4 nm  = pm[cur * 132 + i];
        const float4 neb = pe[cur * 132 + i];
        const ME n3 = {nm.w, __float_as_int(neb.w)};
        const ME b0 = upd2(a0, n3, f0.B0);
        const ME l1 = upd3(a1, a0, n3, skip1, f0.p10);
        const ME b2 = upd2(a2, a1, f0.B0);
        const ME l3 = upd3(a3, a2, a1, skip3, f0.p30);
        a0 = b0; a1 = l1; a2 = b2; a3 = l3;
    }
#undef CTC_ITER

    __syncthreads();
    afin[4 * i + 0] = (float)a0.E + lg2f(a0.m);
    afin[4 * i + 1] = (float)a1.E + lg2f(a1.m);
    afin[4 * i + 2] = (float)a2.E + lg2f(a2.m);
    afin[4 * i + 3] = (float)a3.E + lg2f(a3.m);
    __syncthreads();

    if (tid == 0) {
        const float l1 = afin[2 * llen];
        const float l2 = afin[2 * llen - 1];
        const float mx = fmaxf(l1, l2), mn = fminf(l1, l2);
        const float ls = mx + lg2f(1.0f + ex2f(mn - mx));
        const float nll = -ls * LN2;
        d_loss[b] = (nll < 5e8f) ? nll / (float)llen : 0.f;
    }

    // ---- last CTC block reduces all 64 losses (losses ordered by ticket) ----
    __threadfence();
    __syncthreads();
    if (tid == 0) {
        *fin = (atomicAdd(&d_done, 1) == B_ - 1) ? 1 : 0;
        if (*fin) {
            __threadfence();                 // acquire side of ticket
            float s = 0.f;
            for (int q = 0; q < B_; q++) s += d_loss[q];
            out[0] = s * (1.f / (float)B_);
        }
    }
}

__global__ __launch_bounds__(128) void fused_kernel(
    const float* __restrict__ F, const float* __restrict__ bias,
    const int* __restrict__ labels, const int* __restrict__ flens,
    const int* __restrict__ llens, float* __restrict__ out)
{
    if (blockIdx.x < B_) ctc_path(labels, flens, llens, out);
    else                 gemm_path(F, bias);
}

// =====================================================================
extern "C" void kernel_launch(void* const* d_in, const int* in_sizes, int n_in,
                              void* d_out, int out_size)
{
    (void)in_sizes; (void)n_in; (void)out_size;
    const float* F      = (const float*)d_in[0];
    const float* W      = (const float*)d_in[1];
    const float* bias   = (const float*)d_in[2];
    const int*   labels = (const int*)d_in[3];
    const int*   flens  = (const int*)d_in[4];
    const int*   llens  = (const int*)d_in[5];
    float* out = (float*)d_out;

    cudaFuncSetAttribute(fused_kernel,
                         cudaFuncAttributeMaxDynamicSharedMemorySize, SMEM_FUSED);

    pre_kernel<<<33, 128>>>(W);
    fused_kernel<<<GRID_F, 128, SMEM_FUSED>>>(F, bias, labels, flens, llens, out);
}

// round 17
// speedup vs baseline: 1.3435x; 1.0967x over previous
#include <cuda_runtime.h>
#include <math.h>
#include <stdint.h>

#define B_    64
#define T_    1000
#define D_    512
#define V_    29
#define L_    200
#define CBLANK 28
#define LOG2E 1.44269504088896340736f
#define LN2   0.69314718055994530942f
#define ESENT (-(1 << 29))

#define CHUNK  125
#define NCHUNK 8
#define NGEMM  (NCHUNK * B_)      // 512 producer blocks
#define GRID_F (B_ + NGEMM)       // 576 blocks

typedef unsigned long long u64;

// ---------------- device scratch (no allocations allowed) ----------------
__device__ float d_lp[(long)B_ * T_ * V_];   // LINEAR probs p[b][t][v]
__device__ float d_loss[B_];
__device__ float d_wT[32 * 512];             // transposed W (CTC blocks build)
__device__ int   d_flag[NCHUNK * B_];        // [chunk][sample] ready flags
__device__ int   d_wcnt;                     // W-transpose completion count
__device__ int   d_pdone;                    // producer completion count
__device__ int   d_done;                     // CTC completion ticket

__device__ __forceinline__ float ex2f(float x){ float r; asm("ex2.approx.f32 %0, %1;" : "=f"(r) : "f"(x)); return r; }
__device__ __forceinline__ float lg2f(float x){ float r; asm("lg2.approx.f32 %0, %1;" : "=f"(r) : "f"(x)); return r; }

#define FMA2(d, a, b) asm("fma.rn.f32x2 %0, %1, %2, %0;" : "+l"(d) : "l"(a), "l"(b))

// ---- linear (mantissa, int-exponent) arithmetic (proven R11/R13/R14) ----
struct ME { float m; int E; };

__device__ __forceinline__ float mkscale(int d) {
    return __uint_as_float((unsigned)max(d + 127, 0) << 23);
}
__device__ __forceinline__ ME me_renorm(float v, int Em) {
    const unsigned bits = __float_as_uint(v);
    ME r;
    r.E = Em + (int)(bits >> 23) - 127;
    r.m = __uint_as_float((bits & 0x007fffffu) | 0x3f800000u);
    return r;
}
__device__ __forceinline__ ME me_split(float v) { return me_renorm(v, 0); }
__device__ __forceinline__ ME upd2(ME a, ME b, float p) {
    const int Em = max(a.E, b.E);
    const float sum = fmaf(a.m, mkscale(a.E - Em), b.m * mkscale(b.E - Em));
    return me_renorm(p * sum, Em);
}
__device__ __forceinline__ ME upd3(ME a, ME b, ME c, bool sk, float p) {
    const int Ec = sk ? c.E : ESENT;
    const int Em = max(a.E, max(b.E, Ec));
    const float sum = fmaf(a.m, mkscale(a.E - Em),
                      fmaf(b.m, mkscale(b.E - Em), c.m * mkscale(Ec - Em)));
    return me_renorm(p * sum, Em);
}

// ---- sync helpers ----
__device__ __forceinline__ int ld_acq(const int* p) {
    int v;
    asm volatile("ld.acquire.gpu.global.b32 %0, [%1];" : "=r"(v) : "l"(p) : "memory");
    return v;
}
__device__ __forceinline__ void st_rel(int* p, int v) {
    asm volatile("st.release.gpu.global.b32 [%0], %1;" :: "l"(p), "r"(v) : "memory");
}

// =====================================================================
// Fused single kernel: blocks [0,64) = CTC consumers (+W transpose +
// final reduce + state reset), [64,576) = GEMM producers.
// 128 threads/block, dynamic smem 42496B.
// =====================================================================
#define SMEM_FUSED 42496
extern __shared__ char smem_dyn[];

__device__ void gemm_path(const float* __restrict__ F,
                          const float* __restrict__ bias)
{
    float* fbuf = (float*)smem_dyn;                  // 2 x 128x32 f (32768B)
    float* wt   = (float*)(smem_dyn + 32768);        // 2 x 32x36 f  (9216B)
    float* csh  = (float*)(smem_dyn + 41984);        // 128 f
    float* lbuf = fbuf;                              // epilogue reuse

    const int tid = threadIdx.x;
    const int gb  = blockIdx.x - B_;
    const int c   = gb >> 6;          // chunk 0..7
    const int b   = gb & 63;          // sample
    const long rowBase = (long)b * T_ + c * CHUNK;
    const uint32_t fsh  = (uint32_t)__cvta_generic_to_shared(fbuf);
    const uint32_t wtsh = (uint32_t)__cvta_generic_to_shared(wt);

    // wait for W transpose (done by CTC blocks at kernel start)
    if (tid == 0) { while (ld_acq(&d_wcnt) < B_) __nanosleep(64); }
    __syncthreads();

    auto prefetch = [&](int kci, int st) {
        const uint32_t sbase = fsh + (uint32_t)st * 16384u;
#pragma unroll
        for (int m = 0; m < 8; m++) {
            const int q  = tid + 128 * m;            // 0..1023
            const int r  = q >> 3;
            const int kq = q & 7;
            long row = rowBase + r;
            if (row > (long)B_ * T_ - 1) row = (long)B_ * T_ - 1;   // tail clamp
            const float* src = F + row * D_ + kci * 32 + kq * 4;
            const uint32_t dst = sbase +
                (uint32_t)((r * 32 + ((kq ^ ((r >> 3) & 7)) << 2)) * 4);
            asm volatile("cp.async.ca.shared.global [%0], [%1], 16;" :: "r"(dst), "l"(src));
        }
        const uint32_t wbase = wtsh + (uint32_t)st * 4608u;
#pragma unroll
        for (int m = 0; m < 2; m++) {
            const int q   = tid + 128 * m;           // 0..255
            const int col = q >> 3;
            const int kq  = q & 7;
            const float* src = d_wT + col * 512 + kci * 32 + kq * 4;
            const uint32_t dst = wbase + (uint32_t)((col * 36 + kq * 4) * 4);
            asm volatile("cp.async.ca.shared.global [%0], [%1], 16;" :: "r"(dst), "l"(src));
        }
    };

    prefetch(0, 0);
    asm volatile("cp.async.commit_group;");

    const int rg = tid >> 3;          // 0..15 : rows rg*8 + i
    const int cg = tid & 7;           // 0..7  : cols cg + 8*j
    const int fkey = (rg & 7) << 2;

    float bv[4];
#pragma unroll
    for (int j = 0; j < 4; j++) { int cc = cg + 8 * j; bv[j] = (cc < V_) ? bias[cc] : 0.f; }

    u64 acc[8][4];
#pragma unroll
    for (int i = 0; i < 8; i++)
#pragma unroll
        for (int j = 0; j < 4; j++) acc[i][j] = 0ull;

    for (int kci = 0; kci < 16; kci++) {
        if (kci < 15) prefetch(kci + 1, (kci + 1) & 1);
        asm volatile("cp.async.commit_group;");
        asm volatile("cp.async.wait_group 1;");
        __syncthreads();

        const float* fstage = fbuf + (kci & 1) * 4096;
        const float* wstage = wt   + (kci & 1) * 1152;
#pragma unroll
        for (int kq = 0; kq < 8; kq++) {
            ulonglong2 f[8], w4[4];
#pragma unroll
            for (int i = 0; i < 8; i++)
                f[i] = *reinterpret_cast<const ulonglong2*>(
                    fstage + (rg * 8 + i) * 32 + ((kq << 2) ^ fkey));
#pragma unroll
            for (int j = 0; j < 4; j++)
                w4[j] = *reinterpret_cast<const ulonglong2*>(
                    wstage + (cg + 8 * j) * 36 + kq * 4);
#pragma unroll
            for (int i = 0; i < 8; i++)
#pragma unroll
                for (int j = 0; j < 4; j++) FMA2(acc[i][j], f[i].x, w4[j].x);
#pragma unroll
            for (int i = 0; i < 8; i++)
#pragma unroll
                for (int j = 0; j < 4; j++) FMA2(acc[i][j], f[i].y, w4[j].y);
        }
        __syncthreads();
    }

    // epilogue: combine k-pairs, bias, logits to smem [128][33]
#pragma unroll
    for (int i = 0; i < 8; i++)
#pragma unroll
        for (int j = 0; j < 4; j++) {
            const float lo = __uint_as_float((unsigned)(acc[i][j] & 0xffffffffull));
            const float hi = __uint_as_float((unsigned)(acc[i][j] >> 32));
            lbuf[(rg * 8 + i) * 33 + (cg + 8 * j)] = lo + hi + bv[j];
        }
    __syncthreads();

    if (tid < CHUNK) {
        const float* r = &lbuf[tid * 33];
        float m = r[0];
#pragma unroll
        for (int v = 1; v < V_; v++) m = fmaxf(m, r[v]);
        float sum = 0.f;
#pragma unroll
        for (int v = 0; v < V_; v++) sum += ex2f((r[v] - m) * LOG2E);
        csh[tid] = m * LOG2E + lg2f(sum);
    }
    __syncthreads();

    float* outp = d_lp + rowBase * V_;
    for (int i = tid; i < CHUNK * V_; i += 128) {
        const int row = i / V_;
        const int v   = i - row * V_;
        outp[i] = ex2f(lbuf[row * 33 + v] * LOG2E - csh[row]);
    }

    __threadfence();
    __syncthreads();
    if (tid == 0) {
        st_rel(&d_flag[c * B_ + b], 1);
        __threadfence();
        atomicAdd(&d_pdone, 1);
    }
}

struct PFv { float B0, B1, p10, p11, p30, p31, V0; };

__device__ void ctc_path(const float* __restrict__ W,
                         const int* __restrict__ labels,
                         const int* __restrict__ flens,
                         const int* __restrict__ llens,
                         float* __restrict__ out)
{
    float4* pm     = (float4*)smem_dyn;              // [2][132]
    float4* pe     = pm + 2 * 132;                   // [2][132]
    int*    lab_sh = (int*)(pe + 2 * 132);           // [200]
    float*  afin   = (float*)(lab_sh + L_);          // [520]
    int*    fin    = (int*)(afin + 520);

    const int b    = blockIdx.x;
    const int tid  = threadIdx.x;
    const int flen = flens[b];
    const int llen = llens[b];

    // ---- W transpose: 64 blocks x 128 thr x 2 = 16384 = 32x512 ----
    {
#pragma unroll
        for (int r = 0; r < 2; r++) {
            const int idx = (b * 128 + tid) * 2 + r;
            const int c = idx & 31, k = idx >> 5;
            d_wT[c * 512 + k] = (c < V_) ? W[k * V_ + c] : 0.f;
        }
        __threadfence();
        __syncthreads();
        if (tid == 0) atomicAdd(&d_wcnt, 1);
    }

    for (int k = tid; k < L_; k += 128) lab_sh[k] = labels[b * L_ + k];
    if (tid == 0) {
        const float4 mpad = make_float4(1.f, 1.f, 1.f, 1.f);
        const float  es   = __int_as_float(ESENT);
        const float4 epad = make_float4(es, es, es, es);
        pm[0] = mpad; pm[132] = mpad;
        pe[0] = epad; pe[132] = epad;
    }
    __syncthreads();

    const int i  = tid;
    const int j1 = min(2 * i,     L_ - 1);
    const int j3 = min(2 * i + 1, L_ - 1);
    const int jv = min(max(2 * i - 1, 0), L_ - 1);
    const int e1 = lab_sh[j1];
    const int e3 = lab_sh[j3];
    const int eV = lab_sh[jv];
    const bool skip1 = (i >= 1) && (e1 != lab_sh[j1 - 1]);
    const bool skip3 = (e3 != lab_sh[j3 - 1]);
    const bool skipv = (i >= 1) && (eV != lab_sh[jv - 1]);

    const float* lpb = d_lp + (long)b * T_ * V_;
    int ready = 0;

    auto wait_rows = [&](int row) {
        const int need = row / CHUNK;
        while (ready <= need) {
            if (ld_acq(&d_flag[ready * B_ + b])) ready++;
            else __nanosleep(128);
        }
    };
    auto loadPF = [&](int tt) {
        PFv f;
        const int r0c = min(tt,     T_ - 1);
        const int r1c = min(tt + 1, T_ - 1);
        wait_rows(r1c);
        const int r0 = r0c * V_, r1 = r1c * V_;
        f.B0 = lpb[r0 + CBLANK]; f.p10 = lpb[r0 + e1];
        f.p30 = lpb[r0 + e3];    f.V0  = lpb[r0 + eV];
        f.B1 = lpb[r1 + CBLANK]; f.p11 = lpb[r1 + e1]; f.p31 = lpb[r1 + e3];
        return f;
    };

    wait_rows(0);
    ME a0 = {1.f, ESENT}, a1 = {1.f, ESENT}, a2 = {1.f, ESENT}, a3 = {1.f, ESENT};
    if (i == 0) { a0 = me_split(lpb[CBLANK]); a1 = me_split(lpb[e1]); }
    pm[i + 1] = make_float4(a0.m, a1.m, a2.m, a3.m);
    pe[i + 1] = make_float4(__int_as_float(a0.E), __int_as_float(a1.E),
                            __int_as_float(a2.E), __int_as_float(a3.E));

    PFv f0 = loadPF(1);
    PFv f1 = loadPF(3);
    __syncthreads();

    int cur = 0;
    int t = 1;

#define CTC_ITER(F) do {                                                         \
    const float4 nm  = pm[cur * 132 + i];                                        \
    const float4 neb = pe[cur * 132 + i];                                        \
    const ME n1 = {nm.y, __float_as_int(neb.y)};                                 \
    const ME n2 = {nm.z, __float_as_int(neb.z)};                                 \
    const ME n3 = {nm.w, __float_as_int(neb.w)};                                 \
    const ME b0 = upd2(a0, n3, F.B0);                                            \
    const ME l1 = upd3(a1, a0, n3, skip1, F.p10);                                \
    const ME b2 = upd2(a2, a1, F.B0);                                            \
    const ME l3 = upd3(a3, a2, a1, skip3, F.p30);                                \
    const ME vv = upd3(n3, n2, n1, skipv, F.V0);                                 \
    a0 = upd2(b0, vv, F.B1);                                                     \
    a1 = upd3(l1, b0, vv, skip1, F.p11);                                         \
    a2 = upd2(b2, l1, F.B1);                                                     \
    a3 = upd3(l3, b2, l1, skip3, F.p31);                                         \
    pm[(cur ^ 1) * 132 + i + 1] = make_float4(a0.m, a1.m, a2.m, a3.m);           \
    pe[(cur ^ 1) * 132 + i + 1] = make_float4(                                   \
        __int_as_float(a0.E), __int_as_float(a1.E),                              \
        __int_as_float(a2.E), __int_as_float(a3.E));                             \
    cur ^= 1;                                                                    \
    __syncthreads();                                                             \
    t += 2;                                                                      \
} while (0)

    while (t + 3 < flen) {
        CTC_ITER(f0); f0 = loadPF(t + 2);
        CTC_ITER(f1); f1 = loadPF(t + 2);
    }
    while (t + 1 < flen) {
        CTC_ITER(f0);
        f0 = f1; f1 = loadPF(t + 2);
    }
    if (t < flen) {
        const float4 nm  = pm[cur * 132 + i];
        const float4 neb = pe[cur * 132 + i];
        const ME n3 = {nm.w, __float_as_int(neb.w)};
        const ME b0 = upd2(a0, n3, f0.B0);
        const ME l1 = upd3(a1, a0, n3, skip1, f0.p10);
        const ME b2 = upd2(a2, a1, f0.B0);
        const ME l3 = upd3(a3, a2, a1, skip3, f0.p30);
        a0 = b0; a1 = l1; a2 = b2; a3 = l3;
    }
#undef CTC_ITER

    __syncthreads();
    afin[4 * i + 0] = (float)a0.E + lg2f(a0.m);
    afin[4 * i + 1] = (float)a1.E + lg2f(a1.m);
    afin[4 * i + 2] = (float)a2.E + lg2f(a2.m);
    afin[4 * i + 3] = (float)a3.E + lg2f(a3.m);
    __syncthreads();

    if (tid == 0) {
        const float l1 = afin[2 * llen];
        const float l2 = afin[2 * llen - 1];
        const float mx = fmaxf(l1, l2), mn = fminf(l1, l2);
        const float ls = mx + lg2f(1.0f + ex2f(mn - mx));
        const float nll = -ls * LN2;
        d_loss[b] = (nll < 5e8f) ? nll / (float)llen : 0.f;
    }

    // ---- last CTC block: reduce + state reset for next replay ----
    __threadfence();
    __syncthreads();
    if (tid == 0) *fin = (atomicAdd(&d_done, 1) == B_ - 1) ? 1 : 0;
    __syncthreads();
    if (*fin) {
        if (tid == 0) { while (ld_acq(&d_pdone) < NGEMM) __nanosleep(128); }
        __syncthreads();
        __threadfence();
        for (int k = tid; k < NCHUNK * B_; k += 128) d_flag[k] = 0;
        if (tid == 0) {
            d_pdone = 0; d_done = 0; d_wcnt = 0;
            float s = 0.f;
            for (int q = 0; q < B_; q++) s += d_loss[q];
            out[0] = s * (1.f / (float)B_);
        }
    }
}

__global__ __launch_bounds__(128) void fused_kernel(
    const float* __restrict__ F, const float* __restrict__ W,
    const float* __restrict__ bias,
    const int* __restrict__ labels, const int* __restrict__ flens,
    const int* __restrict__ llens, float* __restrict__ out)
{
    if (blockIdx.x < B_) ctc_path(W, labels, flens, llens, out);
    else                 gemm_path(F, bias);
}

// =====================================================================
extern "C" void kernel_launch(void* const* d_in, const int* in_sizes, int n_in,
                              void* d_out, int out_size)
{
    (void)in_sizes; (void)n_in; (void)out_size;
    const float* F      = (const float*)d_in[0];
    const float* W      = (const float*)d_in[1];
    const float* bias   = (const float*)d_in[2];
    const int*   labels = (const int*)d_in[3];
    const int*   flens  = (const int*)d_in[4];
    const int*   llens  = (const int*)d_in[5];
    float* out = (float*)d_out;

    cudaFuncSetAttribute(fused_kernel,
                         cudaFuncAttributeMaxDynamicSharedMemorySize, SMEM_FUSED);

    fused_kernel<<<GRID_F, 128, SMEM_FUSED>>>(F, W, bias, labels, flens, llens, out);
}